// round 8
// baseline (speedup 1.0000x reference)
#include <cuda_runtime.h>
#include <cuda_bf16.h>
#include <math.h>
#include <stdint.h>

#define N_NODES 65536
#define N_EDGES 524288
#define HIDDEN 128
#define OUTDIM 10
#define NUM_GRAPHS 64
#define SLOT_CAP 64

// ---------------- scratch (device globals; no allocation allowed) ----------
// quantized A planes: 32 words (128 s8) per node row, k-word-permuted
__device__ __align__(16) static uint32_t g_aqh[(size_t)N_NODES * 32];
__device__ __align__(16) static uint32_t g_aql[(size_t)N_NODES * 32];
__device__ static float    g_sa[N_NODES];
__device__ __align__(16) static float    g_h[(size_t)N_NODES * HIDDEN];
__device__ static int      g_deg[N_NODES];
__device__ static int      g_slots[(size_t)N_NODES * SLOT_CAP];
__device__ static float    g_gsum[NUM_GRAPHS * HIDDEN];
__device__ static float    g_gcnt[NUM_GRAPHS];
__device__ static int      g_is64;
// quantized W planes: [layer][n*32 + permuted word]
__device__ __align__(16) static uint32_t g_wqg[3][HIDDEN * 32];
__device__ __align__(16) static uint32_t g_wqm[3][HIDDEN * 32];
__device__ static float    g_sw[3 * HIDDEN];
__device__ static float    g_swinv[3 * HIDDEN];

// ---------------- helpers ----------------------------------------------------
__device__ __forceinline__ int kperm(int w) {
    return (w & ~7) | (((w & 3) << 1) | ((w >> 2) & 1));
}

__device__ __forceinline__ float elu_fast(float v) {
    return v > 0.0f ? v : (__expf(v) - 1.0f);
}

__device__ __forceinline__ void quant_pair(float q, int& h, int& l) {
    h = __float2int_rn(q);
    h = max(-127, min(127, h));
    float resid = q - (float)h;
    l = __float2int_rn(resid * 256.0f);
    l = max(-128, min(127, l));
}

__device__ __forceinline__ uint32_t pack4(int b0, int b1, int b2, int b3) {
    return (uint32_t)(b0 & 0xFF) | ((uint32_t)(b1 & 0xFF) << 8) |
           ((uint32_t)(b2 & 0xFF) << 16) | ((uint32_t)(b3 & 0xFF) << 24);
}

__device__ __forceinline__ void imma_s8(int* c, uint32_t a0, uint32_t a1,
                                        uint32_t a2, uint32_t a3,
                                        uint32_t b0, uint32_t b1) {
    asm volatile(
        "mma.sync.aligned.m16n8k32.row.col.s32.s8.s8.s32 "
        "{%0,%1,%2,%3}, {%4,%5,%6,%7}, {%8,%9}, {%0,%1,%2,%3};"
        : "+r"(c[0]), "+r"(c[1]), "+r"(c[2]), "+r"(c[3])
        : "r"(a0), "r"(a1), "r"(a2), "r"(a3), "r"(b0), "r"(b1));
}

// ---------------- index dtype detection (1 warp, parallel) -------------------
__global__ void detect_kernel(const unsigned int* __restrict__ w) {
    int lane = threadIdx.x;
    bool zero = true;
#pragma unroll
    for (int j = 0; j < 4; j++) {
        if (w[1 + 2 * (lane + 32 * j)] != 0u) zero = false;
    }
    unsigned int mask = __ballot_sync(0xffffffffu, zero);
    if (lane == 0) g_is64 = (mask == 0xffffffffu) ? 1 : 0;
}

__device__ __forceinline__ int load_idx(const void* p, int i, int is64) {
    if (is64) return (int)((const long long*)p)[i];
    return ((const int*)p)[i];
}

// ---------------- W column scales (one warp per (layer,col)) -----------------
__global__ void wscale_kernel(const float* __restrict__ W1,
                              const float* __restrict__ W2,
                              const float* __restrict__ W3) {
    int blk = blockIdx.x;              // 0..383
    int layer = blk >> 7, col = blk & 127;
    const float* W = (layer == 0) ? W1 : (layer == 1) ? W2 : W3;
    int t = threadIdx.x;               // 0..31
    float m = 0.0f;
#pragma unroll
    for (int j = 0; j < 4; j++)
        m = fmaxf(m, fabsf(__ldg(W + (t + 32 * j) * HIDDEN + col)));
#pragma unroll
    for (int o = 16; o; o >>= 1)
        m = fmaxf(m, __shfl_xor_sync(0xffffffffu, m, o));
    if (t == 0) {
        g_sw[blk] = m * (1.0f / 127.0f);
        g_swinv[blk] = (m > 0.0f) ? (127.0f / m) : 0.0f;
    }
}

// ---------------- prep: zero scratch + W quantize (fused) --------------------
__global__ void prep_kernel(const float* __restrict__ W1,
                            const float* __restrict__ W2,
                            const float* __restrict__ W3) {
    int i = blockIdx.x * blockDim.x + threadIdx.x;
    if (i < N_NODES) g_deg[i] = 0;
    if (i < NUM_GRAPHS * HIDDEN) g_gsum[i] = 0.0f;
    if (i < NUM_GRAPHS) g_gcnt[i] = 0.0f;
    if (i < 3 * HIDDEN * 32) {
        int layer = i / (HIDDEN * 32);
        int rem = i - layer * (HIDDEN * 32);
        int n = rem >> 5, w = rem & 31;
        const float* W = (layer == 0) ? W1 : (layer == 1) ? W2 : W3;
        float inv = g_swinv[layer * HIDDEN + n];
        int gb[4], mb[4];
#pragma unroll
        for (int j = 0; j < 4; j++) {
            float q = __ldg(W + (4 * w + j) * HIDDEN + n) * inv;
            quant_pair(q, gb[j], mb[j]);
        }
        int pos = n * 32 + kperm(w);
        g_wqg[layer][pos] = pack4(gb[0], gb[1], gb[2], gb[3]);
        g_wqm[layer][pos] = pack4(mb[0], mb[1], mb[2], mb[3]);
    }
}

// ---------------- bucketed inverse adjacency ---------------------------------
__global__ void build_kernel(const void* __restrict__ src,
                             const void* __restrict__ dst) {
    int e = blockIdx.x * blockDim.x + threadIdx.x;
    if (e >= N_EDGES) return;
    int is64 = g_is64;
    int d = load_idx(dst, e, is64);
    int s = load_idx(src, e, is64);
    int pos = atomicAdd(&g_deg[d], 1);
    if (pos < SLOT_CAP) g_slots[(size_t)d * SLOT_CAP + pos] = s;
}

// ---------------- gather-sum -> quantized s8 hi/lo planes --------------------
__global__ void gather_kernel(const float* __restrict__ hin,
                              uint32_t* __restrict__ aqh,
                              uint32_t* __restrict__ aql,
                              float* __restrict__ saout) {
    int w = (blockIdx.x * blockDim.x + threadIdx.x) >> 5;
    int lane = threadIdx.x & 31;
    if (w >= N_NODES) return;
    int deg = g_deg[w];
    if (deg > SLOT_CAP) deg = SLOT_CAP;
    const int* slots = g_slots + (size_t)w * SLOT_CAP;
    int s0 = (lane < deg) ? slots[lane] : 0;
    int s1 = (32 + lane < deg) ? slots[32 + lane] : 0;
    float4 acc = make_float4(0.f, 0.f, 0.f, 0.f);
    for (int i = 0; i < deg; i++) {
        int s = __shfl_sync(0xffffffffu, (i < 32) ? s0 : s1, i & 31);
        float4 v = __ldg((const float4*)(hin + (size_t)s * HIDDEN) + lane);
        acc.x += v.x; acc.y += v.y; acc.z += v.z; acc.w += v.w;
    }
    // row max -> scale
    float m = fmaxf(fmaxf(fabsf(acc.x), fabsf(acc.y)),
                    fmaxf(fabsf(acc.z), fabsf(acc.w)));
#pragma unroll
    for (int o = 16; o; o >>= 1)
        m = fmaxf(m, __shfl_xor_sync(0xffffffffu, m, o));
    float inv = (m > 0.0f) ? (127.0f / m) : 0.0f;
    int h0, l0, h1, l1, h2, l2, h3, l3;
    quant_pair(acc.x * inv, h0, l0);
    quant_pair(acc.y * inv, h1, l1);
    quant_pair(acc.z * inv, h2, l2);
    quant_pair(acc.w * inv, h3, l3);
    size_t rowOff = (size_t)w * 32;
    int pos = kperm(lane);
    aqh[rowOff + pos] = pack4(h0, h1, h2, h3);
    aql[rowOff + pos] = pack4(l0, l1, l2, l3);
    if (lane == 0) saout[w] = m * (1.0f / 127.0f);
}

// ---------------- persistent s8x3 imma GEMM -----------------------------------
// 296 CTAs loop over 64-row tiles. 256 threads = 8 warps (2M x 4N), warp 32x32.
// SMEM stride 40 words -> conflict-free LDS.64 ((4*gq+tq)%16 distinct).
#define AS_STR 40
#define SM_AH 0
#define SM_AL (64 * AS_STR)
#define SM_WG (2 * 64 * AS_STR)
#define SM_WM (2 * 64 * AS_STR + 128 * AS_STR)
#define GEMM_SMEM_WORDS (2 * 64 * AS_STR + 2 * 128 * AS_STR)
#define GEMM_SMEM_BYTES (GEMM_SMEM_WORDS * 4)
#define GEMM_GRID 296
#define NUM_TILES (N_NODES / 64)

__global__ void __launch_bounds__(256, 2)
gemm_tc_kernel(const uint32_t* __restrict__ Aqh, const uint32_t* __restrict__ Aql,
               const float* __restrict__ sa,
               const uint32_t* __restrict__ Wg, const uint32_t* __restrict__ Wm,
               const float* __restrict__ sw,
               const float* __restrict__ b, float* __restrict__ out) {
    extern __shared__ __align__(16) uint32_t smem[];
    int tid = threadIdx.x;
    int lane = tid & 31, wid = tid >> 5;
    int gq = lane >> 2, tq = lane & 3;
    int warp_m = wid & 1, warp_n = wid >> 1;
    const int mBase = warp_m * 32;
    const int nBase = warp_n * 32;

    // ---- stage W planes once (128 cols x 8 uint4 each plane) ----
    {
        const uint4* src_g = (const uint4*)Wg;
        const uint4* src_m = (const uint4*)Wm;
        for (int i = tid; i < 128 * 8; i += 256) {
            int n = i >> 3, c4 = i & 7;
            *(uint4*)(smem + SM_WG + n * AS_STR + c4 * 4) = __ldg(src_g + i);
            *(uint4*)(smem + SM_WM + n * AS_STR + c4 * 4) = __ldg(src_m + i);
        }
    }

    int tile = blockIdx.x;
    uint4 ph[2], pl[2];
    if (tile < NUM_TILES) {
        const uint4* src_h = (const uint4*)(Aqh + (size_t)tile * 64 * 32);
        const uint4* src_l = (const uint4*)(Aql + (size_t)tile * 64 * 32);
#pragma unroll
        for (int j = 0; j < 2; j++) {
            ph[j] = __ldg(src_h + tid + 256 * j);
            pl[j] = __ldg(src_l + tid + 256 * j);
        }
    }
    __syncthreads();

    while (tile < NUM_TILES) {
        // ---- commit prefetched A (64 rows x 8 uint4 per plane) ----
#pragma unroll
        for (int j = 0; j < 2; j++) {
            int i = tid + 256 * j;
            int r = i >> 3, c4 = i & 7;
            *(uint4*)(smem + SM_AH + r * AS_STR + c4 * 4) = ph[j];
            *(uint4*)(smem + SM_AL + r * AS_STR + c4 * 4) = pl[j];
        }
        __syncthreads();

        int next = tile + GEMM_GRID;
        if (next < NUM_TILES) {
            const uint4* src_h = (const uint4*)(Aqh + (size_t)next * 64 * 32);
            const uint4* src_l = (const uint4*)(Aql + (size_t)next * 64 * 32);
#pragma unroll
            for (int j = 0; j < 2; j++) {
                ph[j] = __ldg(src_h + tid + 256 * j);
                pl[j] = __ldg(src_l + tid + 256 * j);
            }
        }

        int accHG[2][4][4], accX[2][4][4];
#pragma unroll
        for (int mi = 0; mi < 2; mi++)
#pragma unroll
            for (int ni = 0; ni < 4; ni++)
#pragma unroll
                for (int r = 0; r < 4; r++) {
                    accHG[mi][ni][r] = 0;
                    accX[mi][ni][r] = 0;
                }

#pragma unroll
        for (int ks = 0; ks < 4; ks++) {
            int kw = ks * 8 + 2 * tq;
            uint2 ah[2][2], al[2][2];
#pragma unroll
            for (int mi = 0; mi < 2; mi++) {
                int r = mBase + mi * 16 + gq;
                ah[mi][0] = *(const uint2*)(smem + SM_AH + r * AS_STR + kw);
                ah[mi][1] = *(const uint2*)(smem + SM_AH + (r + 8) * AS_STR + kw);
                al[mi][0] = *(const uint2*)(smem + SM_AL + r * AS_STR + kw);
                al[mi][1] = *(const uint2*)(smem + SM_AL + (r + 8) * AS_STR + kw);
            }
            uint2 bg[4], bm[4];
#pragma unroll
            for (int ni = 0; ni < 4; ni++) {
                int c = nBase + ni * 8 + gq;
                bg[ni] = *(const uint2*)(smem + SM_WG + c * AS_STR + kw);
                bm[ni] = *(const uint2*)(smem + SM_WM + c * AS_STR + kw);
            }
#pragma unroll
            for (int mi = 0; mi < 2; mi++)
#pragma unroll
                for (int ni = 0; ni < 4; ni++) {
                    imma_s8(accHG[mi][ni], ah[mi][0].x, ah[mi][1].x, ah[mi][0].y, ah[mi][1].y,
                            bg[ni].x, bg[ni].y);
                    imma_s8(accX[mi][ni], ah[mi][0].x, ah[mi][1].x, ah[mi][0].y, ah[mi][1].y,
                            bm[ni].x, bm[ni].y);
                    imma_s8(accX[mi][ni], al[mi][0].x, al[mi][1].x, al[mi][0].y, al[mi][1].y,
                            bg[ni].x, bg[ni].y);
                }
        }

        // ---- epilogue: dequant + bias + fast ELU + store ----
        size_t rowBase = (size_t)tile * 64;
#pragma unroll
        for (int mi = 0; mi < 2; mi++) {
            int r0 = mBase + mi * 16 + gq;
            float saA = __ldg(sa + rowBase + r0);
            float saB = __ldg(sa + rowBase + r0 + 8);
#pragma unroll
            for (int ni = 0; ni < 4; ni++) {
                int c0 = nBase + ni * 8 + 2 * tq;
                float sw0 = __ldg(sw + c0), sw1 = __ldg(sw + c0 + 1);
                float2 bb = __ldg((const float2*)(b + c0));
                float f0 = ((float)accHG[mi][ni][0] + (float)accX[mi][ni][0] * (1.0f / 256.0f)) * saA * sw0;
                float f1 = ((float)accHG[mi][ni][1] + (float)accX[mi][ni][1] * (1.0f / 256.0f)) * saA * sw1;
                float f2 = ((float)accHG[mi][ni][2] + (float)accX[mi][ni][2] * (1.0f / 256.0f)) * saB * sw0;
                float f3 = ((float)accHG[mi][ni][3] + (float)accX[mi][ni][3] * (1.0f / 256.0f)) * saB * sw1;
                float v0 = elu_fast(f0 + bb.x);
                float v1 = elu_fast(f1 + bb.y);
                float v2 = elu_fast(f2 + bb.x);
                float v3 = elu_fast(f3 + bb.y);
                *(float2*)(out + (rowBase + r0) * HIDDEN + c0) = make_float2(v0, v1);
                *(float2*)(out + (rowBase + r0 + 8) * HIDDEN + c0) = make_float2(v2, v3);
            }
        }
        __syncthreads();
        tile = next;
    }
}

// ---------------- graph readout (sums + counts fused) -------------------------
__global__ void readout_kernel(const float* __restrict__ h,
                               const void* __restrict__ gid) {
    int t = threadIdx.x;
    int base = blockIdx.x * 128;
    int is64 = g_is64;
    int cur = load_idx(gid, base, is64);
    float acc = 0.0f;
    int runlen = 0;
    for (int n = 0; n < 128; n++) {
        int node = base + n;
        int g = load_idx(gid, node, is64);
        if (g != cur) {
            atomicAdd(&g_gsum[cur * HIDDEN + t], acc);
            if (t == 0) atomicAdd(&g_gcnt[cur], (float)runlen);
            acc = 0.0f; runlen = 0; cur = g;
        }
        acc += h[(size_t)node * HIDDEN + t];
        runlen++;
    }
    atomicAdd(&g_gsum[cur * HIDDEN + t], acc);
    if (t == 0) atomicAdd(&g_gcnt[cur], (float)runlen);
}

__global__ void classifier_kernel(const float* __restrict__ Wc,
                                  const float* __restrict__ bc,
                                  float* __restrict__ out) {
    int t = blockIdx.x * blockDim.x + threadIdx.x;
    if (t >= NUM_GRAPHS * OUTDIM) return;
    int g = t / OUTDIM, o = t % OUTDIM;
    float c = fmaxf(g_gcnt[g], 1.0f);
    float inv = 1.0f / c;
    float acc = bc[o];
#pragma unroll 8
    for (int k = 0; k < HIDDEN; k++)
        acc += g_gsum[g * HIDDEN + k] * inv * Wc[k * OUTDIM + o];
    out[t] = acc;
}

// ---------------- launch -------------------------------------------------------
extern "C" void kernel_launch(void* const* d_in, const int* in_sizes, int n_in,
                              void* d_out, int out_size) {
    const float* features = (const float*)d_in[0];
    const void*  src      = d_in[1];
    const void*  dst      = d_in[2];
    const void*  gids     = d_in[3];
    const float* W1 = (const float*)d_in[4];
    const float* b1 = (const float*)d_in[5];
    const float* W2 = (const float*)d_in[6];
    const float* b2 = (const float*)d_in[7];
    const float* W3 = (const float*)d_in[8];
    const float* b3 = (const float*)d_in[9];
    const float* Wc = (const float*)d_in[10];
    const float* bc = (const float*)d_in[11];
    float* out = (float*)d_out;

    uint32_t* aqh; cudaGetSymbolAddress((void**)&aqh, g_aqh);
    uint32_t* aql; cudaGetSymbolAddress((void**)&aql, g_aql);
    float* sa;     cudaGetSymbolAddress((void**)&sa, g_sa);
    float* h;      cudaGetSymbolAddress((void**)&h, g_h);
    uint32_t* wqg; cudaGetSymbolAddress((void**)&wqg, g_wqg);
    uint32_t* wqm; cudaGetSymbolAddress((void**)&wqm, g_wqm);
    float* sw;     cudaGetSymbolAddress((void**)&sw, g_sw);

    cudaFuncSetAttribute(gemm_tc_kernel,
                         cudaFuncAttributeMaxDynamicSharedMemorySize, GEMM_SMEM_BYTES);

    detect_kernel<<<1, 32>>>((const unsigned int*)src);
    wscale_kernel<<<3 * HIDDEN, 32>>>(W1, W2, W3);
    prep_kernel<<<N_NODES / 256, 256>>>(W1, W2, W3);
    build_kernel<<<N_EDGES / 256, 256>>>(src, dst);

    const int GATHER_BLOCKS = (N_NODES * 32) / 256;
    const int WSZ = HIDDEN * 32;

    gather_kernel<<<GATHER_BLOCKS, 256>>>(features, aqh, aql, sa);
    gemm_tc_kernel<<<GEMM_GRID, 256, GEMM_SMEM_BYTES>>>(aqh, aql, sa, wqg, wqm, sw, b1, h);
    gather_kernel<<<GATHER_BLOCKS, 256>>>(h, aqh, aql, sa);
    gemm_tc_kernel<<<GEMM_GRID, 256, GEMM_SMEM_BYTES>>>(aqh, aql, sa, wqg + WSZ, wqm + WSZ, sw + HIDDEN, b2, h);
    gather_kernel<<<GATHER_BLOCKS, 256>>>(h, aqh, aql, sa);
    gemm_tc_kernel<<<GEMM_GRID, 256, GEMM_SMEM_BYTES>>>(aqh, aql, sa, wqg + 2 * WSZ, wqm + 2 * WSZ, sw + 2 * HIDDEN, b3, h);

    readout_kernel<<<N_NODES / 128, 128>>>(h, gids);
    classifier_kernel<<<1, NUM_GRAPHS * OUTDIM>>>(Wc, bc, out);
}

// round 9
// speedup vs baseline: 1.3663x; 1.3663x over previous
#include <cuda_runtime.h>
#include <cuda_bf16.h>
#include <math.h>
#include <stdint.h>

#define N_NODES 65536
#define N_EDGES 524288
#define HIDDEN 128
#define OUTDIM 10
#define NUM_GRAPHS 64
#define SLOT_CAP 64

// ---------------- scratch (device globals; no allocation allowed) ----------
__device__ __align__(16) static uint32_t g_ahi[(size_t)N_NODES * 64];
__device__ __align__(16) static uint32_t g_alo[(size_t)N_NODES * 64];
__device__ __align__(16) static float    g_h[(size_t)N_NODES * HIDDEN];
__device__ static int      g_deg[N_NODES];
__device__ static int      g_slots[(size_t)N_NODES * SLOT_CAP];
__device__ static float    g_gsum[NUM_GRAPHS * HIDDEN];
__device__ static float    g_gcnt[NUM_GRAPHS];
__device__ static int      g_is64;
__device__ __align__(16) static uint32_t g_whi[3][HIDDEN * 64];
__device__ __align__(16) static uint32_t g_wlo[3][HIDDEN * 64];

// ---------------- helpers ----------------------------------------------------
__device__ __forceinline__ int kperm(int w) {
    return (w & ~7) | (((w & 3) << 1) | ((w >> 2) & 1));
}

__device__ __forceinline__ void bf16_split(float v, uint16_t& h, uint16_t& l) {
    __nv_bfloat16 hb = __float2bfloat16(v);
    float r = v - __bfloat162float(hb);
    __nv_bfloat16 lb = __float2bfloat16(r);
    h = __bfloat16_as_ushort(hb);
    l = __bfloat16_as_ushort(lb);
}

__device__ __forceinline__ float elu_fast(float v) {
    return v > 0.0f ? v : (__expf(v) - 1.0f);
}

__device__ __forceinline__ void mma_bf16(float* c, uint32_t a0, uint32_t a1,
                                         uint32_t a2, uint32_t a3,
                                         uint32_t b0, uint32_t b1) {
    asm volatile(
        "mma.sync.aligned.m16n8k16.row.col.f32.bf16.bf16.f32 "
        "{%0,%1,%2,%3}, {%4,%5,%6,%7}, {%8,%9}, {%0,%1,%2,%3};"
        : "+f"(c[0]), "+f"(c[1]), "+f"(c[2]), "+f"(c[3])
        : "r"(a0), "r"(a1), "r"(a2), "r"(a3), "r"(b0), "r"(b1));
}

// ---------------- index dtype detection (1 warp, parallel) -------------------
__global__ void detect_kernel(const unsigned int* __restrict__ w) {
    int lane = threadIdx.x;
    bool zero = true;
#pragma unroll
    for (int j = 0; j < 4; j++) {
        if (w[1 + 2 * (lane + 32 * j)] != 0u) zero = false;
    }
    unsigned int mask = __ballot_sync(0xffffffffu, zero);
    if (lane == 0) g_is64 = (mask == 0xffffffffu) ? 1 : 0;
}

__device__ __forceinline__ int load_idx(const void* p, int i, int is64) {
    if (is64) return (int)((const long long*)p)[i];
    return ((const int*)p)[i];
}

// ---------------- prep: zero scratch + W split (fused) ------------------------
__global__ void prep_kernel(const float* __restrict__ W1,
                            const float* __restrict__ W2,
                            const float* __restrict__ W3) {
    int i = blockIdx.x * blockDim.x + threadIdx.x;
    if (i < N_NODES) g_deg[i] = 0;
    if (i < NUM_GRAPHS * HIDDEN) g_gsum[i] = 0.0f;
    if (i < NUM_GRAPHS) g_gcnt[i] = 0.0f;
    if (i < 3 * HIDDEN * 64) {
        int layer = i / (HIDDEN * 64);
        int rem = i - layer * (HIDDEN * 64);
        int n = rem >> 6, w = rem & 63;
        const float* W = (layer == 0) ? W1 : (layer == 1) ? W2 : W3;
        float v0 = __ldg(W + (2 * w) * HIDDEN + n);
        float v1 = __ldg(W + (2 * w + 1) * HIDDEN + n);
        uint16_t h0, l0, h1, l1;
        bf16_split(v0, h0, l0);
        bf16_split(v1, h1, l1);
        int pos = n * 64 + kperm(w);
        g_whi[layer][pos] = (uint32_t)h0 | ((uint32_t)h1 << 16);
        g_wlo[layer][pos] = (uint32_t)l0 | ((uint32_t)l1 << 16);
    }
}

// ---------------- bucketed inverse adjacency ---------------------------------
__global__ void build_kernel(const void* __restrict__ src,
                             const void* __restrict__ dst) {
    int e = blockIdx.x * blockDim.x + threadIdx.x;
    if (e >= N_EDGES) return;
    int is64 = g_is64;
    int d = load_idx(dst, e, is64);
    int s = load_idx(src, e, is64);
    int pos = atomicAdd(&g_deg[d], 1);
    if (pos < SLOT_CAP) g_slots[(size_t)d * SLOT_CAP + pos] = s;
}

// ---------------- gather-sum -> bf16 hi/lo planes (simple loop, R6-proven) ----
__global__ void gather_kernel(const float* __restrict__ hin,
                              uint32_t* __restrict__ ahi,
                              uint32_t* __restrict__ alo) {
    int w = (blockIdx.x * blockDim.x + threadIdx.x) >> 5;
    int lane = threadIdx.x & 31;
    if (w >= N_NODES) return;
    int deg = g_deg[w];
    if (deg > SLOT_CAP) deg = SLOT_CAP;
    const int* slots = g_slots + (size_t)w * SLOT_CAP;
    int s0 = (lane < deg) ? slots[lane] : 0;
    int s1 = (32 + lane < deg) ? slots[32 + lane] : 0;
    float4 acc = make_float4(0.f, 0.f, 0.f, 0.f);
    for (int i = 0; i < deg; i++) {
        int s = __shfl_sync(0xffffffffu, (i < 32) ? s0 : s1, i & 31);
        float4 v = __ldg((const float4*)(hin + (size_t)s * HIDDEN) + lane);
        acc.x += v.x; acc.y += v.y; acc.z += v.z; acc.w += v.w;
    }
    uint16_t hx, lx, hy, ly, hz, lz, hw, lw;
    bf16_split(acc.x, hx, lx);
    bf16_split(acc.y, hy, ly);
    bf16_split(acc.z, hz, lz);
    bf16_split(acc.w, hw, lw);
    size_t rowOff = (size_t)w * 64;
    int p0 = kperm(2 * lane), p1 = kperm(2 * lane + 1);
    ahi[rowOff + p0] = (uint32_t)hx | ((uint32_t)hy << 16);
    ahi[rowOff + p1] = (uint32_t)hz | ((uint32_t)hw << 16);
    alo[rowOff + p0] = (uint32_t)lx | ((uint32_t)ly << 16);
    alo[rowOff + p1] = (uint32_t)lz | ((uint32_t)lw << 16);
}

// ---------------- persistent bf16x3 mma GEMM (R7-proven) ----------------------
#define AS_STR 68
#define SM_AH 0
#define SM_AL (64 * AS_STR)
#define SM_WH (2 * 64 * AS_STR)
#define SM_WL (2 * 64 * AS_STR + 128 * AS_STR)
#define GEMM_SMEM_WORDS (2 * 64 * AS_STR + 2 * 128 * AS_STR)
#define GEMM_SMEM_BYTES (GEMM_SMEM_WORDS * 4)
#define GEMM_GRID 296
#define NUM_TILES (N_NODES / 64)

__global__ void __launch_bounds__(256, 2)
gemm_tc_kernel(const uint32_t* __restrict__ Ahi, const uint32_t* __restrict__ Alo,
               const uint32_t* __restrict__ Wh, const uint32_t* __restrict__ Wl,
               const float* __restrict__ b, float* __restrict__ out) {
    extern __shared__ __align__(16) uint32_t smem[];
    int tid = threadIdx.x;
    int lane = tid & 31, wid = tid >> 5;
    int gq = lane >> 2, tq = lane & 3;
    int warp_m = wid & 1, warp_n = wid >> 1;
    const int mBase = warp_m * 32;
    const int nBase = warp_n * 32;

    // ---- stage W planes once ----
    {
        const uint4* src_h = (const uint4*)Wh;
        const uint4* src_l = (const uint4*)Wl;
        for (int i = tid; i < 128 * 16; i += 256) {
            int n = i >> 4, c4 = i & 15;
            *(uint4*)(smem + SM_WH + n * AS_STR + c4 * 4) = __ldg(src_h + i);
            *(uint4*)(smem + SM_WL + n * AS_STR + c4 * 4) = __ldg(src_l + i);
        }
    }

    int tile = blockIdx.x;
    uint4 pa[4], pl[4];
    if (tile < NUM_TILES) {
        const uint4* src_h = (const uint4*)(Ahi + (size_t)tile * 64 * 64);
        const uint4* src_l = (const uint4*)(Alo + (size_t)tile * 64 * 64);
#pragma unroll
        for (int j = 0; j < 4; j++) {
            pa[j] = __ldg(src_h + tid + 256 * j);
            pl[j] = __ldg(src_l + tid + 256 * j);
        }
    }
    __syncthreads();

    while (tile < NUM_TILES) {
        // ---- commit prefetched A to SMEM ----
#pragma unroll
        for (int j = 0; j < 4; j++) {
            int i = tid + 256 * j;
            int r = i >> 4, c4 = i & 15;
            *(uint4*)(smem + SM_AH + r * AS_STR + c4 * 4) = pa[j];
            *(uint4*)(smem + SM_AL + r * AS_STR + c4 * 4) = pl[j];
        }
        __syncthreads();

        // ---- prefetch next tile's A (overlaps mainloop) ----
        int next = tile + GEMM_GRID;
        if (next < NUM_TILES) {
            const uint4* src_h = (const uint4*)(Ahi + (size_t)next * 64 * 64);
            const uint4* src_l = (const uint4*)(Alo + (size_t)next * 64 * 64);
#pragma unroll
            for (int j = 0; j < 4; j++) {
                pa[j] = __ldg(src_h + tid + 256 * j);
                pl[j] = __ldg(src_l + tid + 256 * j);
            }
        }

        float acc[2][4][4];
#pragma unroll
        for (int mi = 0; mi < 2; mi++)
#pragma unroll
            for (int ni = 0; ni < 4; ni++)
#pragma unroll
                for (int r = 0; r < 4; r++) acc[mi][ni][r] = 0.0f;

#pragma unroll
        for (int ks = 0; ks < 8; ks++) {
            int kw = ks * 8 + 2 * tq;
            uint2 ah[2][2], al[2][2];
#pragma unroll
            for (int mi = 0; mi < 2; mi++) {
                int r = mBase + mi * 16 + gq;
                ah[mi][0] = *(const uint2*)(smem + SM_AH + r * AS_STR + kw);
                ah[mi][1] = *(const uint2*)(smem + SM_AH + (r + 8) * AS_STR + kw);
                al[mi][0] = *(const uint2*)(smem + SM_AL + r * AS_STR + kw);
                al[mi][1] = *(const uint2*)(smem + SM_AL + (r + 8) * AS_STR + kw);
            }
            uint2 bh[4], bl[4];
#pragma unroll
            for (int ni = 0; ni < 4; ni++) {
                int c = nBase + ni * 8 + gq;
                bh[ni] = *(const uint2*)(smem + SM_WH + c * AS_STR + kw);
                bl[ni] = *(const uint2*)(smem + SM_WL + c * AS_STR + kw);
            }
#pragma unroll
            for (int mi = 0; mi < 2; mi++)
#pragma unroll
                for (int ni = 0; ni < 4; ni++) {
                    mma_bf16(acc[mi][ni], ah[mi][0].x, ah[mi][1].x, ah[mi][0].y, ah[mi][1].y,
                             bh[ni].x, bh[ni].y);
                    mma_bf16(acc[mi][ni], ah[mi][0].x, ah[mi][1].x, ah[mi][0].y, ah[mi][1].y,
                             bl[ni].x, bl[ni].y);
                    mma_bf16(acc[mi][ni], al[mi][0].x, al[mi][1].x, al[mi][0].y, al[mi][1].y,
                             bh[ni].x, bh[ni].y);
                }
        }

        // ---- epilogue: bias + fast ELU + store ----
        size_t rowBase = (size_t)tile * 64;
#pragma unroll
        for (int mi = 0; mi < 2; mi++) {
            int r0 = mBase + mi * 16 + gq;
#pragma unroll
            for (int ni = 0; ni < 4; ni++) {
                int c0 = nBase + ni * 8 + 2 * tq;
                float2 bb = __ldg((const float2*)(b + c0));
                float v0 = elu_fast(acc[mi][ni][0] + bb.x);
                float v1 = elu_fast(acc[mi][ni][1] + bb.y);
                float v2 = elu_fast(acc[mi][ni][2] + bb.x);
                float v3 = elu_fast(acc[mi][ni][3] + bb.y);
                *(float2*)(out + (rowBase + r0) * HIDDEN + c0) = make_float2(v0, v1);
                *(float2*)(out + (rowBase + r0 + 8) * HIDDEN + c0) = make_float2(v2, v3);
            }
        }
        __syncthreads();
        tile = next;
    }
}

// ---------------- graph readout (sums + counts fused) -------------------------
__global__ void readout_kernel(const float* __restrict__ h,
                               const void* __restrict__ gid) {
    int t = threadIdx.x;
    int base = blockIdx.x * 128;
    int is64 = g_is64;
    int cur = load_idx(gid, base, is64);
    float acc = 0.0f;
    int runlen = 0;
    for (int n = 0; n < 128; n++) {
        int node = base + n;
        int g = load_idx(gid, node, is64);
        if (g != cur) {
            atomicAdd(&g_gsum[cur * HIDDEN + t], acc);
            if (t == 0) atomicAdd(&g_gcnt[cur], (float)runlen);
            acc = 0.0f; runlen = 0; cur = g;
        }
        acc += h[(size_t)node * HIDDEN + t];
        runlen++;
    }
    atomicAdd(&g_gsum[cur * HIDDEN + t], acc);
    if (t == 0) atomicAdd(&g_gcnt[cur], (float)runlen);
}

__global__ void classifier_kernel(const float* __restrict__ Wc,
                                  const float* __restrict__ bc,
                                  float* __restrict__ out) {
    int t = blockIdx.x * blockDim.x + threadIdx.x;
    if (t >= NUM_GRAPHS * OUTDIM) return;
    int g = t / OUTDIM, o = t % OUTDIM;
    float c = fmaxf(g_gcnt[g], 1.0f);
    float inv = 1.0f / c;
    float acc = bc[o];
#pragma unroll 8
    for (int k = 0; k < HIDDEN; k++)
        acc += g_gsum[g * HIDDEN + k] * inv * Wc[k * OUTDIM + o];
    out[t] = acc;
}

// ---------------- launch -------------------------------------------------------
extern "C" void kernel_launch(void* const* d_in, const int* in_sizes, int n_in,
                              void* d_out, int out_size) {
    const float* features = (const float*)d_in[0];
    const void*  src      = d_in[1];
    const void*  dst      = d_in[2];
    const void*  gids     = d_in[3];
    const float* W1 = (const float*)d_in[4];
    const float* b1 = (const float*)d_in[5];
    const float* W2 = (const float*)d_in[6];
    const float* b2 = (const float*)d_in[7];
    const float* W3 = (const float*)d_in[8];
    const float* b3 = (const float*)d_in[9];
    const float* Wc = (const float*)d_in[10];
    const float* bc = (const float*)d_in[11];
    float* out = (float*)d_out;

    uint32_t* ahi; cudaGetSymbolAddress((void**)&ahi, g_ahi);
    uint32_t* alo; cudaGetSymbolAddress((void**)&alo, g_alo);
    float* h;      cudaGetSymbolAddress((void**)&h, g_h);
    uint32_t* whi; cudaGetSymbolAddress((void**)&whi, g_whi);
    uint32_t* wlo; cudaGetSymbolAddress((void**)&wlo, g_wlo);

    cudaFuncSetAttribute(gemm_tc_kernel,
                         cudaFuncAttributeMaxDynamicSharedMemorySize, GEMM_SMEM_BYTES);

    detect_kernel<<<1, 32>>>((const unsigned int*)src);
    prep_kernel<<<N_NODES / 256, 256>>>(W1, W2, W3);
    build_kernel<<<N_EDGES / 256, 256>>>(src, dst);

    const int GATHER_BLOCKS = (N_NODES * 32) / 256;
    const int WSZ = HIDDEN * 64;

    gather_kernel<<<GATHER_BLOCKS, 256>>>(features, ahi, alo);
    gemm_tc_kernel<<<GEMM_GRID, 256, GEMM_SMEM_BYTES>>>(ahi, alo, whi, wlo, b1, h);
    gather_kernel<<<GATHER_BLOCKS, 256>>>(h, ahi, alo);
    gemm_tc_kernel<<<GEMM_GRID, 256, GEMM_SMEM_BYTES>>>(ahi, alo, whi + WSZ, wlo + WSZ, b2, h);
    gather_kernel<<<GATHER_BLOCKS, 256>>>(h, ahi, alo);
    gemm_tc_kernel<<<GEMM_GRID, 256, GEMM_SMEM_BYTES>>>(ahi, alo, whi + 2 * WSZ, wlo + 2 * WSZ, b3, h);

    readout_kernel<<<N_NODES / 128, 128>>>(h, gids);
    classifier_kernel<<<1, NUM_GRAPHS * OUTDIM>>>(Wc, bc, out);
}